// round 16
// baseline (speedup 1.0000x reference)
#include <cuda_runtime.h>
#include <cooperative_groups.h>
#include <cstdint>

namespace cg = cooperative_groups;

// Problem dims (fixed by the dataset)
#define HH   256
#define WW   256
#define NWF  129                 // W/2+1
#define FREQ (HH*NWF)            // 33024 frequency bins
#define NB   16                  // batch
#define NC   32                  // in channels
#define NO   32                  // out channels

// Frequency-domain scratch, layout [img][wf][h]  (h contiguous!)
__device__ float2 g_Xf[NB*NC*FREQ];   // 135 MB
__device__ float2 g_Kf[NO*NC*FREQ];   // 270 MB
__device__ float2 g_Of[NB*NO*FREQ];   // 135 MB
__device__ float2 g_tw[256];          // forward twiddles e^{-2pi i k/256}

// ---------------------------------------------------------------------------
__global__ void init_tw_kernel() {
    int k = threadIdx.x;
    double s, c;
    sincospi((double)k / 128.0, &s, &c);   // angle = 2*pi*k/256
    g_tw[k] = make_float2((float)c, (float)(-s));
}

// ---------------------------------------------------------------------------
__device__ __forceinline__ float2 cadd(float2 a, float2 b) {
    return make_float2(a.x + b.x, a.y + b.y);
}
__device__ __forceinline__ float2 csub(float2 a, float2 b) {
    return make_float2(a.x - b.x, a.y - b.y);
}
__device__ __forceinline__ float2 cmul(float2 a, float2 b) {
    return make_float2(a.x*b.x - a.y*b.y, a.x*b.y + a.y*b.x);
}
__device__ __forceinline__ float2 cmulc(float2 a, float2 w) {  // a*conj(w)
    return make_float2(a.x*w.x + a.y*w.y, a.y*w.x - a.x*w.y);
}
template<int INV>
__device__ __forceinline__ float2 mul_mi(float2 a) {
    return INV ? make_float2(-a.y, a.x) : make_float2(a.y, -a.x);
}

// ---------------------------------------------------------------------------
// 8-point DFT in registers, natural order in/out. INV=1 => conj-DFT (=8*IDFT).
// ---------------------------------------------------------------------------
template<int INV>
__device__ __forceinline__ void fft8(float2 a[8]) {
    float2 s0 = cadd(a[0], a[4]), d0 = csub(a[0], a[4]);
    float2 s1 = cadd(a[2], a[6]), d1 = csub(a[2], a[6]);
    float2 e0 = cadd(s0, s1);
    float2 e2 = csub(s0, s1);
    float2 d1i = mul_mi<INV>(d1);
    float2 e1 = cadd(d0, d1i);
    float2 e3 = csub(d0, d1i);
    float2 t0 = cadd(a[1], a[5]), u0 = csub(a[1], a[5]);
    float2 t1 = cadd(a[3], a[7]), u1 = csub(a[3], a[7]);
    float2 o0 = cadd(t0, t1);
    float2 o2 = csub(t0, t1);
    float2 u1i = mul_mi<INV>(u1);
    float2 o1 = cadd(u0, u1i);
    float2 o3 = csub(u0, u1i);
    const float s = 0.70710678118654752f;
    float2 w1o1 = INV ? make_float2(s*(o1.x - o1.y), s*(o1.y + o1.x))
                      : make_float2(s*(o1.x + o1.y), s*(o1.y - o1.x));
    float2 w2o2 = mul_mi<INV>(o2);
    float2 w3o3 = INV ? make_float2(s*(-o3.x - o3.y), s*( o3.x - o3.y))
                      : make_float2(s*(-o3.x + o3.y), s*(-o3.x - o3.y));
    a[0] = cadd(e0, o0);   a[4] = csub(e0, o0);
    a[1] = cadd(e1, w1o1); a[5] = csub(e1, w1o1);
    a[2] = cadd(e2, w2o2); a[6] = csub(e2, w2o2);
    a[3] = cadd(e3, w3o3); a[7] = csub(e3, w3o3);
}

// ---------------------------------------------------------------------------
// Warp-cooperative 256-pt FFT. Entry: a[n1] = x[32*n1 + lane].
// Exit:  a[k1] = X[8*brev5(lane) + k1].
// ---------------------------------------------------------------------------
template<int INV>
__device__ __forceinline__ void warp_fft256(float2 a[8], int lane,
                                            const float2* tw) {
    fft8<INV>(a);
    #pragma unroll
    for (int k1 = 1; k1 < 8; k1++) {
        float2 w = tw[lane * k1];
        if (INV) w.y = -w.y;
        a[k1] = cmul(a[k1], w);
    }
    #pragma unroll
    for (int st = 0; st < 5; st++) {
        const int h = 16 >> st;
        int j = lane & (h - 1);
        float2 w = tw[j * (128 / h)];
        if (INV) w.y = -w.y;
        bool upper = (lane & h) != 0;
        #pragma unroll
        for (int r = 0; r < 8; r++) {
            float px = __shfl_xor_sync(0xffffffffu, a[r].x, h);
            float py = __shfl_xor_sync(0xffffffffu, a[r].y, h);
            if (upper) {
                float2 d = make_float2(px - a[r].x, py - a[r].y);
                a[r] = (h == 1) ? d : cmul(d, w);
            } else {
                a[r].x += px;
                a[r].y += py;
            }
        }
    }
}

// ---------------------------------------------------------------------------
// Exact mirror-inverse of warp_fft256<0>: consumes the forward's register
// layout (a[k1] at lane), returns natural order a[n1]=x[32*n1+lane], times 256.
// ---------------------------------------------------------------------------
__device__ __forceinline__ void warp_ifft256_rev(float2 a[8], int lane,
                                                 const float2* tw) {
    #pragma unroll
    for (int st = 0; st < 5; st++) {
        const int h = 1 << st;
        int j = lane & (h - 1);
        float2 w = tw[j * (128 / h)];
        bool upper = (lane & h) != 0;
        #pragma unroll
        for (int r = 0; r < 8; r++) {
            if (upper && h > 1) a[r] = cmulc(a[r], w);   // de-twiddle
            float px = __shfl_xor_sync(0xffffffffu, a[r].x, h);
            float py = __shfl_xor_sync(0xffffffffu, a[r].y, h);
            if (upper) a[r] = make_float2(px - a[r].x, py - a[r].y);
            else       { a[r].x += px; a[r].y += py; }
        }
    }
    #pragma unroll
    for (int k1 = 1; k1 < 8; k1++)
        a[k1] = cmulc(a[k1], tw[lane * k1]);
    fft8<1>(a);
}

// ---------------------------------------------------------------------------
// FUSED forward 2D rFFT: row FFTs + column FFTs of one image per 2-CTA
// cluster; half-spectrum held in distributed shared memory (no DRAM
// intermediate). CTA rank r owns wf band [r==0: 0..64, r==1: 65..128],
// stored as float4 rows [row][j(128)] with j XOR (row&15) swizzle
// (A=rows 2j, B=2j+1 of the image packed per float4).
// grid = nimg*2 (cluster pairs), block 256.
// Output: [img][wf][h] with scrambled column order (matches cols_fwd).
// ---------------------------------------------------------------------------
__global__ void __launch_bounds__(256) __cluster_dims__(2, 1, 1)
fused_fwd_kernel(const float* __restrict__ in, float2* __restrict__ outf) {
    cg::cluster_group cluster = cg::this_cluster();
    const int rank = (int)cluster.block_rank();

    extern __shared__ __align__(16) float4 spec[];   // [65 rows][128 j]
    __shared__ float2 Sz[8*264];
    __shared__ float2 tw[256];

    const int t = threadIdx.x, w = t >> 5, lane = t & 31;
    tw[t] = g_tw[t];
    __syncthreads();

    const int n = blockIdx.x >> 1;        // image index (rank = blockIdx.x&1)

    // ---- phase 1: 64 row-pair FFTs (8 per warp), scatter to owner CTA ----
    float2* S = Sz + w * 264;
    for (int pp = 0; pp < 8; pp++) {
        const int p  = w*8 + pp;                       // local pair 0..63
        const int h0 = rank*128 + 2*p;                 // image rows h0, h0+1
        const float* rowA = in + ((size_t)n*HH + h0) * WW;
        float2 a[8];
        #pragma unroll
        for (int n1 = 0; n1 < 8; n1++) {
            int i = 32*n1 + lane;
            a[n1] = make_float2(rowA[i], rowA[WW + i]);
        }
        warp_fft256<0>(a, lane, tw);
        const int kr = __brev(lane) >> 27;
        __syncwarp();
        #pragma unroll
        for (int k1 = 0; k1 < 8; k1++)
            S[k1*33 + kr] = a[k1];
        __syncwarp();
        // unpack + scatter: A[k] -> (wf=k, h0), B[k] -> (wf=k, h0+1)
        const int j = h0 >> 1;                         // float4 column
        #pragma unroll
        for (int m = 0; m < 4; m++) {
            int k  = lane + 32*m;
            int kn = (256 - k) & 255;
            float2 Zk = S[(k  & 7)*33 + (k  >> 3)];
            float2 Zn = S[(kn & 7)*33 + (kn >> 3)];
            float4 v;
            v.x = 0.5f*(Zk.x + Zn.x); v.y = 0.5f*(Zk.y - Zn.y);  // A (row h0)
            v.z = 0.5f*(Zk.y + Zn.y); v.w = 0.5f*(Zn.x - Zk.x);  // B (h0+1)
            int ro  = (k <= 64) ? 0 : 1;
            int row = (ro == 0) ? k : k - 65;
            float4* base = (ro == rank) ? spec
                         : (float4*)cluster.map_shared_rank(spec, ro);
            base[row*128 + (j ^ (row & 15))] = v;
        }
        if (lane == 0) {                               // k = 128 (Zn = Zk)
            float2 Zk = S[0*33 + 16];
            float4 v = make_float4(Zk.x, 0.f, Zk.y, 0.f);
            int row = 128 - 65;                        // owner CTA1, row 63
            float4* base = (rank == 1) ? spec
                         : (float4*)cluster.map_shared_rank(spec, 1);
            base[row*128 + (j ^ (row & 15))] = v;
        }
        __syncwarp();                                  // S reuse next iter
    }
    cluster.sync();                                    // all scatters visible

    // ---- phase 2: column FFTs on owned wf rows, stream to gmem ----
    const int nrows = (rank == 0) ? 65 : 64;
    for (int row = w; row < nrows; row += 8) {
        const int wf = (rank == 0) ? row : 65 + row;
        const int sw = row & 15;
        float2 a[8];
        #pragma unroll
        for (int n1 = 0; n1 < 8; n1++) {
            int h = 32*n1 + lane;
            int jj = (h >> 1) ^ sw;
            const float2* cell = (const float2*)&spec[row*128 + jj];
            a[n1] = cell[h & 1];
        }
        warp_fft256<0>(a, lane, tw);
        float2* orow = outf + (size_t)n*FREQ + (size_t)wf*HH;
        #pragma unroll
        for (int k1 = 0; k1 < 8; k1++)
            orow[32*k1 + lane] = a[k1];
    }
}

// ---------------------------------------------------------------------------
// Inverse column FFT consuming the scrambled order; natural order out.
// ---------------------------------------------------------------------------
__global__ void __launch_bounds__(256)
fft_cols_inv_kernel(float2* __restrict__ data, float scale) {
    __shared__ float2 tw[256];
    const int t = threadIdx.x, w = t >> 5, lane = t & 31;
    tw[t] = g_tw[t];
    __syncthreads();
    const int n  = blockIdx.x / 17;
    const int wf = (blockIdx.x % 17) * 8 + w;
    if (wf > 128) return;
    float2* row = data + (size_t)n*FREQ + (size_t)wf*HH;
    float2 a[8];
    #pragma unroll
    for (int k1 = 0; k1 < 8; k1++) a[k1] = row[32*k1 + lane];
    warp_ifft256_rev(a, lane, tw);
    #pragma unroll
    for (int n1 = 0; n1 < 8; n1++) {
        float2 v = a[n1];
        row[32*n1 + lane] = make_float2(v.x*scale, v.y*scale);
    }
}

// ---------------------------------------------------------------------------
// Tensor-core einsum: Of[b,o,f] = sum_c Xf[b,c,f] * Kf[o,c,f]
// f-tile = 16 (full 128B lines). 512 threads, 16 warps, ONE bin per warp.
// Round-9 staging layout + fragment math (conflict-free LDS).
// Register-side tf32 hi/lo split; negation trick for real part.
// ---------------------------------------------------------------------------
__device__ __forceinline__ void split2u(float v, unsigned& h, unsigned& l) {
    unsigned hv = __float_as_uint(v) & 0xFFFFE000u;
    float lf = v - __uint_as_float(hv);
    h = hv;
    l = __float_as_uint(lf) & 0xFFFFE000u;
}

#define MMA8(D, A, B)                                                        \
    asm volatile("mma.sync.aligned.m16n8k8.row.col.f32.tf32.tf32.f32 "       \
                 "{%0,%1,%2,%3},{%4,%5,%6,%7},{%8,%9},{%0,%1,%2,%3};"        \
                 : "+f"(D[0]), "+f"(D[1]), "+f"(D[2]), "+f"(D[3])            \
                 : "r"(A[0]), "r"(A[1]), "r"(A[2]), "r"(A[3]),               \
                   "r"(B[0]), "r"(B[1]))

__global__ void __launch_bounds__(512, 2)
einsum_tc_kernel(const float2* __restrict__ Xf,
                 const float2* __restrict__ Kf,
                 float2* __restrict__ Of) {
    extern __shared__ __align__(16) float2 SB2[];
    float2* XS = SB2;
    float2* KS = SB2 + 2048;

    const int t    = threadIdx.x;          // 0..511
    const int w    = t >> 5;               // warp = bin f (0..15)
    const int lane = t & 31;
    const int f0   = blockIdx.x * 16;

    float Pre[4][4], Pim[4][4];
    #pragma unroll
    for (int ot = 0; ot < 4; ot++)
        #pragma unroll
        for (int j = 0; j < 4; j++) {
            Pre[ot][j] = 0.f;
            Pim[ot][j] = 0.f;
        }

    // loader roles: 2 threads per tile row, 4 float4 each
    const int rowX = t >> 1;               // X: valid for t<256 (rows 0..127)
    const int half = t & 1;
    const int bXr  = rowX >> 3, cXr = rowX & 7;
    const int lnX  = ((bXr & 7) << 2) | (cXr & 3);
    const int rX   = (bXr >> 3) | ((cXr >> 2) << 1);
    const int rowK = t >> 1;               // K rows 0..255
    const int oKr  = rowK >> 3, cKr = rowK & 7;
    const int lnK  = ((oKr & 7) << 2) | (cKr & 3);
    const int slotK = (oKr >> 3)*2 + (cKr >> 2);

    for (int cs = 0; cs < 4; cs++) {
        const int c0 = cs * 8;
        __syncthreads();                   // prior compute reads done
        if (t < 256) {                     // X tile: 128 rows x 128B
            const float4* src = (const float4*)
                (Xf + ((size_t)(bXr*NC + c0 + cXr))*FREQ + f0);
            #pragma unroll
            for (int qq = 0; qq < 4; qq++) {
                int q = half*4 + qq;
                float4 v = src[q];
                XS[(rX*16 + 2*q    )*32 + lnX] = make_float2(v.x, v.y);
                XS[(rX*16 + 2*q + 1)*32 + lnX] = make_float2(v.z, v.w);
            }
        }
        {                                  // K tile: 256 rows x 128B
            const float4* src = (const float4*)
                (Kf + ((size_t)(oKr*NC + c0 + cKr))*FREQ + f0);
            #pragma unroll
            for (int qq = 0; qq < 4; qq++) {
                int q = half*4 + qq;
                float4 v = src[q];
                KS[((slotK)*16 + 2*q    )*32 + lnK] = make_float2(v.x, v.y);
                KS[((slotK)*16 + 2*q + 1)*32 + lnK] = make_float2(v.z, v.w);
            }
        }
        __syncthreads();                   // tile visible
        unsigned arh[4], arl[4], aih[4], ail[4];
        #pragma unroll
        for (int r = 0; r < 4; r++) {
            float2 v = XS[(r*16 + w)*32 + lane];
            split2u(v.x, arh[r], arl[r]);
            split2u(v.y, aih[r], ail[r]);
        }
        #pragma unroll
        for (int ot = 0; ot < 4; ot++) {
            unsigned brh[2], brl[2], bih[2], bil[2], nbh[2], nbl[2];
            #pragma unroll
            for (int r = 0; r < 2; r++) {
                float2 v = KS[((ot*2 + r)*16 + w)*32 + lane];
                split2u(v.x, brh[r], brl[r]);
                split2u(v.y, bih[r], bil[r]);
                nbh[r] = bih[r] ^ 0x80000000u;
                nbl[r] = bil[r] ^ 0x80000000u;
            }
            MMA8(Pre[ot], arh, brh);
            MMA8(Pre[ot], arh, brl);
            MMA8(Pre[ot], arl, brh);
            MMA8(Pre[ot], aih, nbh);
            MMA8(Pre[ot], aih, nbl);
            MMA8(Pre[ot], ail, nbh);
            MMA8(Pim[ot], arh, bih);
            MMA8(Pim[ot], arh, bil);
            MMA8(Pim[ot], arl, bih);
            MMA8(Pim[ot], aih, brh);
            MMA8(Pim[ot], aih, brl);
            MMA8(Pim[ot], ail, brh);
        }
    }
    __syncthreads();                       // all fragment reads done
    float2* OS = SB2;
    #pragma unroll
    for (int ot = 0; ot < 4; ot++)
        #pragma unroll
        for (int j = 0; j < 4; j++) {
            int row = (lane >> 2) + 8*(j >> 1);          // b
            int col = ot*8 + 2*(lane & 3) + (j & 1);     // o
            int rc  = row*32 + col;
            int s   = (((rc >> 5) & 7) << 1) | ((rc >> 1) & 1);
            OS[rc*16 + (w ^ s)] = make_float2(Pre[ot][j], Pim[ot][j]);
        }
    __syncthreads();
    for (int idx = t; idx < 8192; idx += 512) {
        int rc = idx >> 4, f = idx & 15;
        int s  = (((rc >> 5) & 7) << 1) | ((rc >> 1) & 1);
        Of[(size_t)rc*FREQ + f0 + f] = OS[rc*16 + (f ^ s)];
    }
}

// ---------------------------------------------------------------------------
// Inverse real FFT along W from [wf][h] layout; real rows out. grid=nimg*16.
// ---------------------------------------------------------------------------
__global__ void __launch_bounds__(256)
irfft_rows_kernel(const float2* __restrict__ inf, float* __restrict__ out) {
    __shared__ __align__(16) float2 Sload[129*18];  // [k][16 rows], stride 18
    __shared__ float2 Sz[8*264];
    __shared__ float2 tw[256];
    const int t = threadIdx.x, w = t >> 5, lane = t & 31;
    tw[t] = g_tw[t];
    const int n  = blockIdx.x >> 4;
    const int r0 = (blockIdx.x & 15) << 4;
    // coalesced gather of [k][r0..r0+15]
    const float4* src = (const float4*)(inf + (size_t)n*FREQ + r0);
    float4* Sload4 = (float4*)Sload;
    for (int idx = t; idx < 129*8; idx += 256) {
        int k = idx >> 3, cp = idx & 7;
        Sload4[k*9 + cp] = src[(size_t)k*(HH/2) + cp];
    }
    __syncthreads();
    // build Z for pair p=w: rows r0+2w (A), r0+2w+1 (B)
    float2 a[8];
    #pragma unroll
    for (int n1 = 0; n1 < 8; n1++) {
        int i = 32*n1 + lane;
        if (i <= 128) {
            float2 A  = Sload[i*18 + 2*w];
            float2 Bv = Sload[i*18 + 2*w + 1];
            a[n1] = make_float2(A.x - Bv.y, A.y + Bv.x);
        } else {
            int kn = 256 - i;
            float2 A  = Sload[kn*18 + 2*w];
            float2 Bv = Sload[kn*18 + 2*w + 1];
            a[n1] = make_float2(A.x + Bv.y, Bv.x - A.y);
        }
    }
    warp_fft256<1>(a, lane, tw);
    float2* S = Sz + w * 264;
    const int kr = __brev(lane) >> 27;
    const float sc = 1.0f/256.0f;
    #pragma unroll
    for (int k1 = 0; k1 < 8; k1++) {
        float2 v = a[k1];
        S[k1*33 + kr] = make_float2(v.x*sc, v.y*sc);
    }
    __syncwarp();
    float* oA = out + ((size_t)n*HH + r0 + 2*w) * WW;
    #pragma unroll
    for (int m = 0; m < 8; m++) {
        int i = lane + 32*m;
        float2 v = S[(i & 7)*33 + (i >> 3)];
        oA[i]      = v.x;
        oA[WW + i] = v.y;
    }
}

// ---------------------------------------------------------------------------
extern "C" void kernel_launch(void* const* d_in, const int* in_sizes, int n_in,
                              void* d_out, int out_size) {
    const float* x = (const float*)d_in[0];   // (16,32,256,256)
    const float* w = (const float*)d_in[1];   // (32,32,256,256)
    float* out = (float*)d_out;               // (16,32,256,256)

    float2 *Xf, *Kf, *Of;
    cudaGetSymbolAddress((void**)&Xf, g_Xf);
    cudaGetSymbolAddress((void**)&Kf, g_Kf);
    cudaGetSymbolAddress((void**)&Of, g_Of);

    const int SPEC_BYTES = 65 * 128 * 16;   // 133120
    cudaFuncSetAttribute(fused_fwd_kernel,
                         cudaFuncAttributeMaxDynamicSharedMemorySize,
                         SPEC_BYTES);
    cudaFuncSetAttribute(einsum_tc_kernel,
                         cudaFuncAttributeMaxDynamicSharedMemorySize, 65536);

    init_tw_kernel<<<1, 256>>>();

    // fused forward 2D rFFT (rows + cols in one kernel, DSMEM intermediate)
    fused_fwd_kernel<<<NB*NC*2, 256, SPEC_BYTES>>>(x, Xf);
    fused_fwd_kernel<<<NO*NC*2, 256, SPEC_BYTES>>>(w, Kf);

    // frequency-domain channel contraction (512 thr, 1 bin/warp, f-tile 16)
    einsum_tc_kernel<<<FREQ/16, 512, 65536>>>(Xf, Kf, Of);

    // inverse column FFT (consumes scrambled order, 1/256)
    fft_cols_inv_kernel<<<NB*NO*17, 256>>>(Of, 1.0f/256.0f);
    // inverse row FFT (gathers transposed layout, final 1/256)
    irfft_rows_kernel<<<NB*NO*16, 256>>>(Of, out);
}